// round 16
// baseline (speedup 1.0000x reference)
#include <cuda_runtime.h>
#include <cuda_fp16.h>

#define H 128
#define N_X 250000
#define N_SRC 50000
#define N_Y 50000
#define N_INT 500000
#define E_NODE 1000000
#define E_DOM 500000
#define BN_EPS 1e-5f

// ------------------------- scratch (device globals) -------------------------
__device__ float  g_xsum[N_SRC * H];
__device__ __half g_xsum_linh[N_SRC * H];
__device__ __half g_ylinh[N_Y * H];
__device__ __half g_xlinh[N_X * H];
__device__ __half g_Wh[3 * H * H];
__device__ float  g_stats[2 * H];
__device__ float  g_mv[2 * H];

// ------------------------- kernel 0: convert 3 weight matrices to fp16 (proven) ----------------
__global__ void wconvert(const float* __restrict__ W0, const float* __restrict__ W1,
                         const float* __restrict__ W2, __half* __restrict__ Wh) {
    int i = blockIdx.x * blockDim.x + threadIdx.x;
    const float* src = (blockIdx.y == 0) ? W0 : (blockIdx.y == 1) ? W1 : W2;
    float4 v = *reinterpret_cast<const float4*>(&src[i * 4]);
    uint2 t;
    __half2 h0 = __floats2half2_rn(v.x, v.y);
    __half2 h1 = __floats2half2_rn(v.z, v.w);
    t.x = *reinterpret_cast<unsigned*>(&h0);
    t.y = *reinterpret_cast<unsigned*>(&h1);
    *reinterpret_cast<uint2*>(&Wh[(size_t)blockIdx.y * H * H + i * 4]) = t;
}

// ------------------------- kernel 1: x -> domain segment sum (proven) -------------------------
#define RX 125
__global__ void xsum_scatter(const float* __restrict__ x,
                             const int* __restrict__ dom,
                             float* __restrict__ xsum) {
    int c = threadIdx.x;
    int r0 = blockIdx.x * RX;
    int cur = dom[r0];
    float acc = 0.f;
    for (int r = r0; r < r0 + RX; r++) {
        int d = dom[r];
        if (d != cur) {
            atomicAdd(&xsum[(size_t)cur * H + c], acc);
            acc = 0.f;
            cur = d;
        }
        acc += x[(size_t)r * H + c];
    }
    atomicAdd(&xsum[(size_t)cur * H + c], acc);
}

// ------------------------- kernel 2: fp16 tensor-core GEMM (proven R14) -------------------------
#define GR 128
#define PADH 136
#define SMEM_GEMM ((GR + H) * PADH * 2)

__global__ void __launch_bounds__(512, 2)
gemm_tc(const float* __restrict__ in, const __half* __restrict__ Wh16,
        __half* __restrict__ out, int nrows) {
    extern __shared__ __half smh[];
    __half* Ah = smh;
    __half* Wh = smh + GR * PADH;
    int tid = threadIdx.x;
    int lane = tid & 31;
    int w = tid >> 5;
    int rb = blockIdx.x * GR;

    #pragma unroll
    for (int i = 0; i < 4; i++) {
        int cid = i * 512 + tid;
        int n = cid >> 4;
        int q = (cid & 15) * 8;
        uint4 v = *reinterpret_cast<const uint4*>(&Wh16[(size_t)n * H + q]);
        *reinterpret_cast<uint4*>(&Wh[n * PADH + q]) = v;
    }
    #pragma unroll
    for (int i = 0; i < 8; i++) {
        int cid = i * 512 + tid;
        int row = cid >> 5;
        int q = (cid & 31) * 4;
        int grow = rb + row;
        float4 v = make_float4(0.f, 0.f, 0.f, 0.f);
        if (grow < nrows)
            v = *reinterpret_cast<const float4*>(&in[(size_t)grow * H + q]);
        uint2 t;
        __half2 h0 = __floats2half2_rn(v.x, v.y);
        __half2 h1 = __floats2half2_rn(v.z, v.w);
        t.x = *reinterpret_cast<unsigned*>(&h0);
        t.y = *reinterpret_cast<unsigned*>(&h1);
        *reinterpret_cast<uint2*>(&Ah[row * PADH + q]) = t;
    }
    __syncthreads();

    int wm = w & 7;
    int wn = w >> 3;

    float c[8][4];
    #pragma unroll
    for (int j = 0; j < 8; j++)
        #pragma unroll
        for (int q = 0; q < 4; q++) c[j][q] = 0.f;

    int gm = lane >> 2;
    int kq = lane & 3;
    const __half* arow = Ah + (wm * 16 + gm) * PADH + kq * 2;
    const __half* brow = Wh + (wn * 64 + gm) * PADH + kq * 2;

    #pragma unroll
    for (int kt = 0; kt < 8; kt++) {
        int k0 = kt * 16;
        unsigned a0 = *reinterpret_cast<const unsigned*>(arow + k0);
        unsigned a1 = *reinterpret_cast<const unsigned*>(arow + 8 * PADH + k0);
        unsigned a2 = *reinterpret_cast<const unsigned*>(arow + k0 + 8);
        unsigned a3 = *reinterpret_cast<const unsigned*>(arow + 8 * PADH + k0 + 8);
        #pragma unroll
        for (int j = 0; j < 8; j++) {
            unsigned b0 = *reinterpret_cast<const unsigned*>(brow + j * 8 * PADH + k0);
            unsigned b1 = *reinterpret_cast<const unsigned*>(brow + j * 8 * PADH + k0 + 8);
            asm("mma.sync.aligned.m16n8k16.row.col.f32.f16.f16.f32 "
                "{%0,%1,%2,%3}, {%4,%5,%6,%7}, {%8,%9}, {%0,%1,%2,%3};"
                : "+f"(c[j][0]), "+f"(c[j][1]), "+f"(c[j][2]), "+f"(c[j][3])
                : "r"(a0), "r"(a1), "r"(a2), "r"(a3), "r"(b0), "r"(b1));
        }
    }

    int row0 = rb + wm * 16 + gm;
    int row1 = row0 + 8;
    int cbase = wn * 64 + kq * 2;
    #pragma unroll
    for (int j = 0; j < 8; j++) {
        int col = cbase + j * 8;
        if (row0 < nrows)
            *reinterpret_cast<__half2*>(&out[(size_t)row0 * H + col]) =
                __floats2half2_rn(c[j][0], c[j][1]);
        if (row1 < nrows)
            *reinterpret_cast<__half2*>(&out[(size_t)row1 * H + col]) =
                __floats2half2_rn(c[j][2], c[j][3]);
    }
}

// ------------------------- shared gather core for msg passes -------------------------
#define MROWS 64
__device__ __forceinline__ void msg_row_acc(float* acc,
                                            const __half* __restrict__ xlin,
                                            const __half* __restrict__ xsum_lin,
                                            const __half* __restrict__ ylin,
                                            const int* __restrict__ nm0,
                                            int jlo, int jhi, int d0, int d1, int cg) {
    #pragma unroll
    for (int q = 0; q < 8; q++) acc[q] = 0.f;
    for (int j = jlo; j < jhi; j++) {
        uint4 raw = *reinterpret_cast<const uint4*>(&xlin[(size_t)nm0[j] * H + cg]);
        const __half2* h = reinterpret_cast<const __half2*>(&raw);
        #pragma unroll
        for (int p = 0; p < 4; p++) {
            float2 f = __half22float2(h[p]);
            acc[p * 2] += f.x;
            acc[p * 2 + 1] += f.y;
        }
    }
    uint4 rs = *reinterpret_cast<const uint4*>(&xsum_lin[(size_t)d0 * H + cg]);
    uint4 ry = *reinterpret_cast<const uint4*>(&ylin[(size_t)d1 * H + cg]);
    const __half2* hs = reinterpret_cast<const __half2*>(&rs);
    const __half2* hy = reinterpret_cast<const __half2*>(&ry);
    #pragma unroll
    for (int p = 0; p < 4; p++) {
        float2 fs = __half22float2(hs[p]);
        float2 fy = __half22float2(hy[p]);
        acc[p * 2] += fs.x + fy.x;
        acc[p * 2 + 1] += fs.y + fy.y;
    }
}

__device__ __forceinline__ void bsearch_rows(int* s_lo, const int* __restrict__ ii,
                                             int e_base, int tid) {
    if (tid <= MROWS) {
        int target = e_base + tid;
        int lo = 0, hi = E_NODE;
        while (lo < hi) {
            int mid = (lo + hi) >> 1;
            if (ii[mid] < target) lo = mid + 1; else hi = mid;
        }
        s_lo[tid] = lo;
    }
}

// ------------------------- kernel 3: PASS 1 — BN stats only (no msg store) ---------------------
__global__ void __launch_bounds__(256)
msg_stats(const __half* __restrict__ xlin,
          const __half* __restrict__ xsum_lin,
          const __half* __restrict__ ylin,
          const int* __restrict__ nm0,
          const int* __restrict__ ii,
          const int* __restrict__ dm0,
          const int* __restrict__ dm1,
          float* __restrict__ stats) {
    __shared__ int s_lo[MROWS + 1];
    __shared__ float s_sum[2 * H];
    int tid = threadIdx.x;
    int cg = (tid & 15) * 8;
    int stream = tid >> 4;
    int e_base = blockIdx.x * MROWS;

    bsearch_rows(s_lo, ii, e_base, tid);
    if (tid < 2 * H) s_sum[tid] = 0.f;
    __syncthreads();

    float csum[8], csq[8];
    #pragma unroll
    for (int q = 0; q < 8; q++) { csum[q] = 0.f; csq[q] = 0.f; }

    for (int r = stream; r < MROWS; r += 16) {
        int e = e_base + r;
        if (e >= E_DOM) break;
        float acc[8];
        msg_row_acc(acc, xlin, xsum_lin, ylin, nm0, s_lo[r], s_lo[r + 1],
                    dm0[e], dm1[e], cg);
        #pragma unroll
        for (int q = 0; q < 8; q++) {
            csum[q] += acc[q];
            csq[q] += acc[q] * acc[q];
        }
    }

    #pragma unroll
    for (int q = 0; q < 8; q++) {
        atomicAdd(&s_sum[cg + q], csum[q]);
        atomicAdd(&s_sum[H + cg + q], csq[q]);
    }
    __syncthreads();
    if (tid < 2 * H) atomicAdd(&stats[tid], s_sum[tid]);
}

// ------------------------- kernel 4: BN finalize (proven) -------------------------
__global__ void bn_finalize(const float* __restrict__ stats,
                            const float* __restrict__ bn_w,
                            const float* __restrict__ bn_b,
                            float* __restrict__ mv) {
    int c = threadIdx.x;
    float inv_n = 1.f / (float)E_DOM;
    float mean = stats[c] * inv_n;
    float var = stats[H + c] * inv_n - mean * mean;
    float s = bn_w[c] * rsqrtf(var + BN_EPS);
    mv[c] = s;
    mv[H + c] = bn_b[c] - mean * s;
}

// ------------------------- kernel 5: PASS 2 — recompute + normalize + ReLU + scatter -----------
__global__ void __launch_bounds__(256)
msg_scatter(const __half* __restrict__ xlin,
            const __half* __restrict__ xsum_lin,
            const __half* __restrict__ ylin,
            const int* __restrict__ nm0,
            const int* __restrict__ ii,
            const int* __restrict__ dm0,
            const int* __restrict__ dm1,
            const float* __restrict__ mv,
            float* __restrict__ out) {
    __shared__ int s_lo[MROWS + 1];
    int tid = threadIdx.x;
    int cg = (tid & 15) * 8;
    int stream = tid >> 4;
    int e_base = blockIdx.x * MROWS;

    bsearch_rows(s_lo, ii, e_base, tid);
    __syncthreads();

    float4 sc0 = *reinterpret_cast<const float4*>(mv + cg);
    float4 sc1 = *reinterpret_cast<const float4*>(mv + cg + 4);
    float4 sh0 = *reinterpret_cast<const float4*>(mv + H + cg);
    float4 sh1 = *reinterpret_cast<const float4*>(mv + H + cg + 4);

    for (int r = stream; r < MROWS; r += 16) {
        int e = e_base + r;
        if (e >= E_DOM) break;
        int d1 = dm1[e];
        float acc[8];
        msg_row_acc(acc, xlin, xsum_lin, ylin, nm0, s_lo[r], s_lo[r + 1],
                    dm0[e], d1, cg);
        float v0 = fmaxf(fmaf(acc[0], sc0.x, sh0.x), 0.f);
        float v1 = fmaxf(fmaf(acc[1], sc0.y, sh0.y), 0.f);
        float v2 = fmaxf(fmaf(acc[2], sc0.z, sh0.z), 0.f);
        float v3 = fmaxf(fmaf(acc[3], sc0.w, sh0.w), 0.f);
        float v4 = fmaxf(fmaf(acc[4], sc1.x, sh1.x), 0.f);
        float v5 = fmaxf(fmaf(acc[5], sc1.y, sh1.y), 0.f);
        float v6 = fmaxf(fmaf(acc[6], sc1.z, sh1.z), 0.f);
        float v7 = fmaxf(fmaf(acc[7], sc1.w, sh1.w), 0.f);
        float* p = &out[(size_t)d1 * H + cg];
        asm volatile("red.global.add.v4.f32 [%0], {%1,%2,%3,%4};"
                     :: "l"(p), "f"(v0), "f"(v1), "f"(v2), "f"(v3) : "memory");
        asm volatile("red.global.add.v4.f32 [%0], {%1,%2,%3,%4};"
                     :: "l"(p + 4), "f"(v4), "f"(v5), "f"(v6), "f"(v7) : "memory");
    }
}

// ------------------------- launch: multi-stream DAG, streams created ONCE (proven) -------------
extern "C" void kernel_launch(void* const* d_in, const int* in_sizes, int n_in,
                              void* d_out, int out_size) {
    const float* x      = (const float*)d_in[0];
    const float* y      = (const float*)d_in[1];
    const int*   dom    = (const int*)d_in[2];
    const int*   nm     = (const int*)d_in[3];
    const int*   ii     = (const int*)d_in[4];
    const int*   dm     = (const int*)d_in[5];
    const float* W_xsum = (const float*)d_in[6];
    const float* W_xint = (const float*)d_in[7];
    const float* W_y    = (const float*)d_in[8];
    const float* bn_w   = (const float*)d_in[9];
    const float* bn_b   = (const float*)d_in[10];
    float* out = (float*)d_out;

    const int* nm0 = nm;
    const int* dm0 = dm;
    const int* dm1 = dm + E_DOM;

    void *p_xsum, *p_xsum_linh, *p_ylinh, *p_xlinh, *p_stats, *p_mv, *p_wh;
    cudaGetSymbolAddress(&p_xsum, g_xsum);
    cudaGetSymbolAddress(&p_xsum_linh, g_xsum_linh);
    cudaGetSymbolAddress(&p_ylinh, g_ylinh);
    cudaGetSymbolAddress(&p_xlinh, g_xlinh);
    cudaGetSymbolAddress(&p_stats, g_stats);
    cudaGetSymbolAddress(&p_mv, g_mv);
    cudaGetSymbolAddress(&p_wh, g_Wh);

    cudaFuncSetAttribute(gemm_tc, cudaFuncAttributeMaxDynamicSharedMemorySize, SMEM_GEMM);

    __half* Wh_xint = (__half*)p_wh;
    __half* Wh_xsum = (__half*)p_wh + H * H;
    __half* Wh_y    = (__half*)p_wh + 2 * H * H;

    static cudaStream_t s1 = nullptr, s2 = nullptr, s3 = nullptr;
    static cudaEvent_t e0, e1, e2, e3;
    if (s1 == nullptr) {
        cudaStreamCreateWithFlags(&s1, cudaStreamNonBlocking);
        cudaStreamCreateWithFlags(&s2, cudaStreamNonBlocking);
        cudaStreamCreateWithFlags(&s3, cudaStreamNonBlocking);
        cudaEventCreateWithFlags(&e0, cudaEventDisableTiming);
        cudaEventCreateWithFlags(&e1, cudaEventDisableTiming);
        cudaEventCreateWithFlags(&e2, cudaEventDisableTiming);
        cudaEventCreateWithFlags(&e3, cudaEventDisableTiming);
        bn_finalize<<<1, 128, 0, s1>>>((const float*)p_stats, bn_w, bn_b, (float*)p_mv);
        bn_finalize<<<1, 128, 0, s2>>>((const float*)p_stats, bn_w, bn_b, (float*)p_mv);
        bn_finalize<<<1, 128, 0, s3>>>((const float*)p_stats, bn_w, bn_b, (float*)p_mv);
        cudaEventRecord(e0, s1); cudaEventRecord(e1, s1);
        cudaEventRecord(e2, s2); cudaEventRecord(e3, s3);
        cudaStreamWaitEvent(s1, e2, 0);
        cudaStreamWaitEvent(0, e1, 0);
    }

    {
        dim3 g(H * H / 4 / 256, 3);
        wconvert<<<g, 256>>>(W_xint, W_xsum, W_y, (__half*)p_wh);
    }

    // ---- fork
    cudaEventRecord(e0, 0);
    cudaStreamWaitEvent(s1, e0, 0);
    cudaStreamWaitEvent(s2, e0, 0);
    cudaStreamWaitEvent(s3, e0, 0);

    cudaMemsetAsync(p_stats, 0, sizeof(float) * 2 * H, 0);
    cudaMemsetAsync(d_out, 0, sizeof(float) * (size_t)out_size, 0);

    cudaMemsetAsync(p_xsum, 0, sizeof(float) * (size_t)N_SRC * H, s1);
    xsum_scatter<<<N_X / RX, 128, 0, s1>>>(x, dom, (float*)p_xsum);
    gemm_tc<<<(N_SRC + GR - 1) / GR, 512, SMEM_GEMM, s1>>>((const float*)p_xsum, Wh_xsum,
                                                           (__half*)p_xsum_linh, N_SRC);

    gemm_tc<<<(N_X + GR - 1) / GR, 512, SMEM_GEMM, s2>>>(x, Wh_xint, (__half*)p_xlinh, N_X);

    gemm_tc<<<(N_Y + GR - 1) / GR, 512, SMEM_GEMM, s3>>>(y, Wh_y, (__half*)p_ylinh, N_Y);

    // ---- join
    cudaEventRecord(e1, s1);
    cudaEventRecord(e2, s2);
    cudaEventRecord(e3, s3);
    cudaStreamWaitEvent(0, e1, 0);
    cudaStreamWaitEvent(0, e2, 0);
    cudaStreamWaitEvent(0, e3, 0);

    // ---- serial spine: stats -> bn -> scatter (msg never materialized)
    msg_stats<<<(E_DOM + MROWS - 1) / MROWS, 256>>>((const __half*)p_xlinh,
                                                    (const __half*)p_xsum_linh,
                                                    (const __half*)p_ylinh,
                                                    nm0, ii, dm0, dm1, (float*)p_stats);

    bn_finalize<<<1, 128>>>((const float*)p_stats, bn_w, bn_b, (float*)p_mv);

    msg_scatter<<<(E_DOM + MROWS - 1) / MROWS, 256>>>((const __half*)p_xlinh,
                                                      (const __half*)p_xsum_linh,
                                                      (const __half*)p_ylinh,
                                                      nm0, ii, dm0, dm1,
                                                      (const float*)p_mv, out);
}

// round 17
// speedup vs baseline: 1.2128x; 1.2128x over previous
#include <cuda_runtime.h>
#include <cuda_fp16.h>

#define H 128
#define N_X 250000
#define N_SRC 50000
#define N_Y 50000
#define N_INT 500000
#define E_NODE 1000000
#define E_DOM 500000
#define BN_EPS 1e-5f

// ------------------------- scratch (device globals) -------------------------
__device__ float  g_xsum[N_SRC * H];
__device__ __half g_xsum_linh[N_SRC * H];
__device__ __half g_ylinh[N_Y * H];
__device__ __half g_xlinh[N_X * H];
__device__ __half g_msgh[E_DOM * H];
__device__ __half g_Wh[3 * H * H];
__device__ float  g_stats[2 * H];
__device__ float  g_mv[2 * H];

// ------------------------- kernel 0: convert 3 weight matrices to fp16 (proven) ----------------
__global__ void wconvert(const float* __restrict__ W0, const float* __restrict__ W1,
                         const float* __restrict__ W2, __half* __restrict__ Wh) {
    int i = blockIdx.x * blockDim.x + threadIdx.x;
    const float* src = (blockIdx.y == 0) ? W0 : (blockIdx.y == 1) ? W1 : W2;
    float4 v = *reinterpret_cast<const float4*>(&src[i * 4]);
    uint2 t;
    __half2 h0 = __floats2half2_rn(v.x, v.y);
    __half2 h1 = __floats2half2_rn(v.z, v.w);
    t.x = *reinterpret_cast<unsigned*>(&h0);
    t.y = *reinterpret_cast<unsigned*>(&h1);
    *reinterpret_cast<uint2*>(&Wh[(size_t)blockIdx.y * H * H + i * 4]) = t;
}

// ------------------------- kernel 1: x -> domain segment sum (proven) -------------------------
#define RX 125
__global__ void xsum_scatter(const float* __restrict__ x,
                             const int* __restrict__ dom,
                             float* __restrict__ xsum) {
    int c = threadIdx.x;
    int r0 = blockIdx.x * RX;
    int cur = dom[r0];
    float acc = 0.f;
    for (int r = r0; r < r0 + RX; r++) {
        int d = dom[r];
        if (d != cur) {
            atomicAdd(&xsum[(size_t)cur * H + c], acc);
            acc = 0.f;
            cur = d;
        }
        acc += x[(size_t)r * H + c];
    }
    atomicAdd(&xsum[(size_t)cur * H + c], acc);
}

// ------------------------- kernel 2: fp16 tensor-core GEMM (proven R14) -------------------------
#define GR 128
#define PADH 136
#define SMEM_GEMM ((GR + H) * PADH * 2)

__global__ void __launch_bounds__(512, 2)
gemm_tc(const float* __restrict__ in, const __half* __restrict__ Wh16,
        __half* __restrict__ out, int nrows) {
    extern __shared__ __half smh[];
    __half* Ah = smh;
    __half* Wh = smh + GR * PADH;
    int tid = threadIdx.x;
    int lane = tid & 31;
    int w = tid >> 5;
    int rb = blockIdx.x * GR;

    #pragma unroll
    for (int i = 0; i < 4; i++) {
        int cid = i * 512 + tid;
        int n = cid >> 4;
        int q = (cid & 15) * 8;
        uint4 v = *reinterpret_cast<const uint4*>(&Wh16[(size_t)n * H + q]);
        *reinterpret_cast<uint4*>(&Wh[n * PADH + q]) = v;
    }
    #pragma unroll
    for (int i = 0; i < 8; i++) {
        int cid = i * 512 + tid;
        int row = cid >> 5;
        int q = (cid & 31) * 4;
        int grow = rb + row;
        float4 v = make_float4(0.f, 0.f, 0.f, 0.f);
        if (grow < nrows)
            v = *reinterpret_cast<const float4*>(&in[(size_t)grow * H + q]);
        uint2 t;
        __half2 h0 = __floats2half2_rn(v.x, v.y);
        __half2 h1 = __floats2half2_rn(v.z, v.w);
        t.x = *reinterpret_cast<unsigned*>(&h0);
        t.y = *reinterpret_cast<unsigned*>(&h1);
        *reinterpret_cast<uint2*>(&Ah[row * PADH + q]) = t;
    }
    __syncthreads();

    int wm = w & 7;
    int wn = w >> 3;

    float c[8][4];
    #pragma unroll
    for (int j = 0; j < 8; j++)
        #pragma unroll
        for (int q = 0; q < 4; q++) c[j][q] = 0.f;

    int gm = lane >> 2;
    int kq = lane & 3;
    const __half* arow = Ah + (wm * 16 + gm) * PADH + kq * 2;
    const __half* brow = Wh + (wn * 64 + gm) * PADH + kq * 2;

    #pragma unroll
    for (int kt = 0; kt < 8; kt++) {
        int k0 = kt * 16;
        unsigned a0 = *reinterpret_cast<const unsigned*>(arow + k0);
        unsigned a1 = *reinterpret_cast<const unsigned*>(arow + 8 * PADH + k0);
        unsigned a2 = *reinterpret_cast<const unsigned*>(arow + k0 + 8);
        unsigned a3 = *reinterpret_cast<const unsigned*>(arow + 8 * PADH + k0 + 8);
        #pragma unroll
        for (int j = 0; j < 8; j++) {
            unsigned b0 = *reinterpret_cast<const unsigned*>(brow + j * 8 * PADH + k0);
            unsigned b1 = *reinterpret_cast<const unsigned*>(brow + j * 8 * PADH + k0 + 8);
            asm("mma.sync.aligned.m16n8k16.row.col.f32.f16.f16.f32 "
                "{%0,%1,%2,%3}, {%4,%5,%6,%7}, {%8,%9}, {%0,%1,%2,%3};"
                : "+f"(c[j][0]), "+f"(c[j][1]), "+f"(c[j][2]), "+f"(c[j][3])
                : "r"(a0), "r"(a1), "r"(a2), "r"(a3), "r"(b0), "r"(b1));
        }
    }

    int row0 = rb + wm * 16 + gm;
    int row1 = row0 + 8;
    int cbase = wn * 64 + kq * 2;
    #pragma unroll
    for (int j = 0; j < 8; j++) {
        int col = cbase + j * 8;
        if (row0 < nrows)
            *reinterpret_cast<__half2*>(&out[(size_t)row0 * H + col]) =
                __floats2half2_rn(c[j][0], c[j][1]);
        if (row1 < nrows)
            *reinterpret_cast<__half2*>(&out[(size_t)row1 * H + col]) =
                __floats2half2_rn(c[j][2], c[j][3]);
    }
}

// ------------------------- kernel 3: fused message + BN stats (R14 + smem index staging) -------
#define MROWS 64
#define SIDX 320
__global__ void __launch_bounds__(256)
msg_kernel(const __half* __restrict__ xlin,
           const __half* __restrict__ xsum_lin,
           const __half* __restrict__ ylin,
           const int* __restrict__ nm0,
           const int* __restrict__ ii,
           const int* __restrict__ dm0,
           const int* __restrict__ dm1,
           __half* __restrict__ msg,
           float* __restrict__ stats) {
    __shared__ int s_lo[MROWS + 1];
    __shared__ int s_idx[SIDX];
    __shared__ float s_sum[2 * H];
    int tid = threadIdx.x;
    int cg = (tid & 15) * 8;
    int stream = tid >> 4;
    int e_base = blockIdx.x * MROWS;

    if (tid <= MROWS) {
        int target = e_base + tid;
        int lo = 0, hi = E_NODE;
        while (lo < hi) {
            int mid = (lo + hi) >> 1;
            if (ii[mid] < target) lo = mid + 1; else hi = mid;
        }
        s_lo[tid] = lo;
    }
    if (tid < 2 * H) s_sum[tid] = 0.f;
    __syncthreads();

    // stage edge indices for the whole block into smem (capped; fallback to global)
    int j0 = s_lo[0];
    int ntot = s_lo[MROWS] - j0;
    int nstage = min(ntot, SIDX);
    for (int i = tid; i < nstage; i += 256) s_idx[i] = nm0[j0 + i];
    __syncthreads();

    float csum[8], csq[8];
    #pragma unroll
    for (int q = 0; q < 8; q++) { csum[q] = 0.f; csq[q] = 0.f; }

    for (int r = stream; r < MROWS; r += 16) {
        int e = e_base + r;
        if (e >= E_DOM) break;
        float acc[8];
        #pragma unroll
        for (int q = 0; q < 8; q++) acc[q] = 0.f;

        int jend = s_lo[r + 1];
        for (int j = s_lo[r]; j < jend; j++) {
            int off = j - j0;
            int idx = (off < SIDX) ? s_idx[off] : nm0[j];
            uint4 raw = *reinterpret_cast<const uint4*>(&xlin[(size_t)idx * H + cg]);
            const __half2* h = reinterpret_cast<const __half2*>(&raw);
            #pragma unroll
            for (int p = 0; p < 4; p++) {
                float2 f = __half22float2(h[p]);
                acc[p * 2] += f.x;
                acc[p * 2 + 1] += f.y;
            }
        }
        {
            uint4 rs = *reinterpret_cast<const uint4*>(&xsum_lin[(size_t)dm0[e] * H + cg]);
            uint4 ry = *reinterpret_cast<const uint4*>(&ylin[(size_t)dm1[e] * H + cg]);
            const __half2* hs = reinterpret_cast<const __half2*>(&rs);
            const __half2* hy = reinterpret_cast<const __half2*>(&ry);
            #pragma unroll
            for (int p = 0; p < 4; p++) {
                float2 fs = __half22float2(hs[p]);
                float2 fy = __half22float2(hy[p]);
                acc[p * 2] += fs.x + fy.x;
                acc[p * 2 + 1] += fs.y + fy.y;
            }
        }
        uint4 o;
        __half2* oh = reinterpret_cast<__half2*>(&o);
        #pragma unroll
        for (int p = 0; p < 4; p++)
            oh[p] = __floats2half2_rn(acc[p * 2], acc[p * 2 + 1]);
        *reinterpret_cast<uint4*>(&msg[(size_t)e * H + cg]) = o;

        #pragma unroll
        for (int q = 0; q < 8; q++) {
            csum[q] += acc[q];
            csq[q] += acc[q] * acc[q];
        }
    }

    #pragma unroll
    for (int q = 0; q < 8; q++) {
        atomicAdd(&s_sum[cg + q], csum[q]);
        atomicAdd(&s_sum[H + cg + q], csq[q]);
    }
    __syncthreads();
    if (tid < 2 * H) atomicAdd(&stats[tid], s_sum[tid]);
}

// ------------------------- kernel 4: BN finalize (proven) -------------------------
__global__ void bn_finalize(const float* __restrict__ stats,
                            const float* __restrict__ bn_w,
                            const float* __restrict__ bn_b,
                            float* __restrict__ mv) {
    int c = threadIdx.x;
    float inv_n = 1.f / (float)E_DOM;
    float mean = stats[c] * inv_n;
    float var = stats[H + c] * inv_n - mean * mean;
    float s = bn_w[c] * rsqrtf(var + BN_EPS);
    mv[c] = s;
    mv[H + c] = bn_b[c] - mean * s;
}

// ------------------------- kernel 5: normalize + ReLU + scatter (proven) -------------------------
#define ER 128
__global__ void out_scatter(const __half* __restrict__ msg,
                            const int* __restrict__ dm1,
                            const float* __restrict__ mv,
                            float* __restrict__ out) {
    int cg = (threadIdx.x & 31) * 4;
    int ro = threadIdx.x >> 5;
    float4 scale = *reinterpret_cast<const float4*>(mv + cg);
    float4 shift = *reinterpret_cast<const float4*>(mv + H + cg);
    int ebase = blockIdx.x * ER;
    int eend = min(ebase + ER, E_DOM);
    for (int e = ebase + ro; e < eend; e += 4) {
        uint2 raw = *reinterpret_cast<const uint2*>(&msg[(size_t)e * H + cg]);
        float2 m01 = __half22float2(*reinterpret_cast<const __half2*>(&raw.x));
        float2 m23 = __half22float2(*reinterpret_cast<const __half2*>(&raw.y));
        float4 v;
        v.x = fmaxf(fmaf(m01.x, scale.x, shift.x), 0.f);
        v.y = fmaxf(fmaf(m01.y, scale.y, shift.y), 0.f);
        v.z = fmaxf(fmaf(m23.x, scale.z, shift.z), 0.f);
        v.w = fmaxf(fmaf(m23.y, scale.w, shift.w), 0.f);
        float* p = &out[(size_t)dm1[e] * H + cg];
        asm volatile("red.global.add.v4.f32 [%0], {%1,%2,%3,%4};"
                     :: "l"(p), "f"(v.x), "f"(v.y), "f"(v.z), "f"(v.w) : "memory");
    }
}

// ------------------------- launch: multi-stream DAG, streams created ONCE (proven) -------------
extern "C" void kernel_launch(void* const* d_in, const int* in_sizes, int n_in,
                              void* d_out, int out_size) {
    const float* x      = (const float*)d_in[0];
    const float* y      = (const float*)d_in[1];
    const int*   dom    = (const int*)d_in[2];
    const int*   nm     = (const int*)d_in[3];
    const int*   ii     = (const int*)d_in[4];
    const int*   dm     = (const int*)d_in[5];
    const float* W_xsum = (const float*)d_in[6];
    const float* W_xint = (const float*)d_in[7];
    const float* W_y    = (const float*)d_in[8];
    const float* bn_w   = (const float*)d_in[9];
    const float* bn_b   = (const float*)d_in[10];
    float* out = (float*)d_out;

    const int* nm0 = nm;
    const int* dm0 = dm;
    const int* dm1 = dm + E_DOM;

    void *p_xsum, *p_xsum_linh, *p_ylinh, *p_xlinh, *p_msgh, *p_stats, *p_mv, *p_wh;
    cudaGetSymbolAddress(&p_xsum, g_xsum);
    cudaGetSymbolAddress(&p_xsum_linh, g_xsum_linh);
    cudaGetSymbolAddress(&p_ylinh, g_ylinh);
    cudaGetSymbolAddress(&p_xlinh, g_xlinh);
    cudaGetSymbolAddress(&p_msgh, g_msgh);
    cudaGetSymbolAddress(&p_stats, g_stats);
    cudaGetSymbolAddress(&p_mv, g_mv);
    cudaGetSymbolAddress(&p_wh, g_Wh);

    cudaFuncSetAttribute(gemm_tc, cudaFuncAttributeMaxDynamicSharedMemorySize, SMEM_GEMM);

    __half* Wh_xint = (__half*)p_wh;
    __half* Wh_xsum = (__half*)p_wh + H * H;
    __half* Wh_y    = (__half*)p_wh + 2 * H * H;

    static cudaStream_t s1 = nullptr, s2 = nullptr, s3 = nullptr;
    static cudaEvent_t e0, e1, e2, e3;
    if (s1 == nullptr) {
        cudaStreamCreateWithFlags(&s1, cudaStreamNonBlocking);
        cudaStreamCreateWithFlags(&s2, cudaStreamNonBlocking);
        cudaStreamCreateWithFlags(&s3, cudaStreamNonBlocking);
        cudaEventCreateWithFlags(&e0, cudaEventDisableTiming);
        cudaEventCreateWithFlags(&e1, cudaEventDisableTiming);
        cudaEventCreateWithFlags(&e2, cudaEventDisableTiming);
        cudaEventCreateWithFlags(&e3, cudaEventDisableTiming);
        bn_finalize<<<1, 128, 0, s1>>>((const float*)p_stats, bn_w, bn_b, (float*)p_mv);
        bn_finalize<<<1, 128, 0, s2>>>((const float*)p_stats, bn_w, bn_b, (float*)p_mv);
        bn_finalize<<<1, 128, 0, s3>>>((const float*)p_stats, bn_w, bn_b, (float*)p_mv);
        cudaEventRecord(e0, s1); cudaEventRecord(e1, s1);
        cudaEventRecord(e2, s2); cudaEventRecord(e3, s3);
        cudaStreamWaitEvent(s1, e2, 0);
        cudaStreamWaitEvent(0, e1, 0);
    }

    {
        dim3 g(H * H / 4 / 256, 3);
        wconvert<<<g, 256>>>(W_xint, W_xsum, W_y, (__half*)p_wh);
    }

    // ---- fork
    cudaEventRecord(e0, 0);
    cudaStreamWaitEvent(s1, e0, 0);
    cudaStreamWaitEvent(s2, e0, 0);
    cudaStreamWaitEvent(s3, e0, 0);

    cudaMemsetAsync(p_stats, 0, sizeof(float) * 2 * H, 0);
    cudaMemsetAsync(d_out, 0, sizeof(float) * (size_t)out_size, 0);

    cudaMemsetAsync(p_xsum, 0, sizeof(float) * (size_t)N_SRC * H, s1);
    xsum_scatter<<<N_X / RX, 128, 0, s1>>>(x, dom, (float*)p_xsum);
    gemm_tc<<<(N_SRC + GR - 1) / GR, 512, SMEM_GEMM, s1>>>((const float*)p_xsum, Wh_xsum,
                                                           (__half*)p_xsum_linh, N_SRC);

    gemm_tc<<<(N_X + GR - 1) / GR, 512, SMEM_GEMM, s2>>>(x, Wh_xint, (__half*)p_xlinh, N_X);

    gemm_tc<<<(N_Y + GR - 1) / GR, 512, SMEM_GEMM, s3>>>(y, Wh_y, (__half*)p_ylinh, N_Y);

    // ---- join
    cudaEventRecord(e1, s1);
    cudaEventRecord(e2, s2);
    cudaEventRecord(e3, s3);
    cudaStreamWaitEvent(0, e1, 0);
    cudaStreamWaitEvent(0, e2, 0);
    cudaStreamWaitEvent(0, e3, 0);

    msg_kernel<<<(E_DOM + MROWS - 1) / MROWS, 256>>>((const __half*)p_xlinh,
                                                     (const __half*)p_xsum_linh,
                                                     (const __half*)p_ylinh,
                                                     nm0, ii, dm0, dm1,
                                                     (__half*)p_msgh, (float*)p_stats);

    bn_finalize<<<1, 128>>>((const float*)p_stats, bn_w, bn_b, (float*)p_mv);

    out_scatter<<<(E_DOM + ER - 1) / ER, 128>>>((const __half*)p_msgh, dm1,
                                                (const float*)p_mv, out);
}